// round 1
// baseline (speedup 1.0000x reference)
#include <cuda_runtime.h>
#include <math.h>

#define NSRC_MAX 100000
#define NDST_MAX 100000
#define NE_MAX   1600000
#define IND  128
#define OUTD 64

// Scratch (device globals — no allocation allowed)
__device__ float  g_z[NSRC_MAX * OUTD];   // z_src, post-softplus if item_user
__device__ float  g_el[NSRC_MAX];
__device__ float  g_er[NDST_MAX];
__device__ float  g_m[NDST_MAX];          // segment max
__device__ float  g_den[NDST_MAX];        // segment sum of exp
__device__ float  g_e[NE_MAX];            // e, then exp(e - m)
__device__ float4 g_wr[IND / 4];          // W_dst^T @ a_r (128 floats)

// ---------------------------------------------------------------------------
// w_r[k] = sum_o W_dst[o][k] * attn_w[OUTD + o]
__global__ void wr_kernel(const float* __restrict__ Wdst,
                          const float* __restrict__ attn) {
    int k = threadIdx.x;  // 128 threads
    float s = 0.f;
#pragma unroll 8
    for (int o = 0; o < OUTD; ++o) s += Wdst[o * IND + k] * attn[OUTD + o];
    ((float*)g_wr)[k] = s;
}

// ---------------------------------------------------------------------------
// z_src = h_src @ W_src^T  (tile: 64 nodes x 64 outs, 4x4 per thread, 256 thr)
__global__ void __launch_bounds__(256) gemm_z_kernel(
    const float* __restrict__ h, const float* __restrict__ W,
    const int* __restrict__ item_user, int n) {
    __shared__ float4 hs[64 * 17];  // 64 nodes x 16 f4 (+1 pad)
    __shared__ float4 ws[64 * 17];  // 64 outs  x 16 f4 (+1 pad)
    const int tx = threadIdx.x & 15;
    const int ty = threadIdx.x >> 4;
    const int node0 = blockIdx.x * 64;
    float acc[4][4];
#pragma unroll
    for (int i = 0; i < 4; ++i)
#pragma unroll
        for (int j = 0; j < 4; ++j) acc[i][j] = 0.f;

    const float4 zero4 = make_float4(0.f, 0.f, 0.f, 0.f);
    for (int kk = 0; kk < 32; kk += 16) {  // K in float4 units, 2 halves
        __syncthreads();
#pragma unroll
        for (int t = 0; t < 4; ++t) {
            int idx = (int)threadIdx.x + 256 * t;
            int r = idx >> 4, c = idx & 15;
            int node = node0 + r;
            hs[r * 17 + c] = (node < n) ? ((const float4*)h)[node * 32 + kk + c] : zero4;
            ws[r * 17 + c] = ((const float4*)W)[r * 32 + kk + c];
        }
        __syncthreads();
#pragma unroll
        for (int g = 0; g < 16; ++g) {
            float4 hv[4], wv[4];
#pragma unroll
            for (int i = 0; i < 4; ++i) hv[i] = hs[(ty * 4 + i) * 17 + g];
#pragma unroll
            for (int j = 0; j < 4; ++j) wv[j] = ws[(tx + 16 * j) * 17 + g];
#pragma unroll
            for (int i = 0; i < 4; ++i)
#pragma unroll
                for (int j = 0; j < 4; ++j) {
                    acc[i][j] += hv[i].x * wv[j].x;
                    acc[i][j] += hv[i].y * wv[j].y;
                    acc[i][j] += hv[i].z * wv[j].z;
                    acc[i][j] += hv[i].w * wv[j].w;
                }
        }
    }
    const bool sp = (*item_user != 0);
#pragma unroll
    for (int i = 0; i < 4; ++i) {
        int node = node0 + ty * 4 + i;
        if (node < n) {
#pragma unroll
            for (int j = 0; j < 4; ++j) {
                float v = acc[i][j];
                if (sp) v = (v > 20.f) ? v : log1pf(__expf(v));
                g_z[node * OUTD + tx + 16 * j] = v;
            }
        }
    }
}

// ---------------------------------------------------------------------------
// el[n] = z_src[n] . a_l ;  er[n] = h_dst[n] . w_r   (one warp per node)
__global__ void el_er_kernel(const float* __restrict__ hdst,
                             const float* __restrict__ attn,
                             int nsrc, int ndst) {
    int gw = (int)((blockIdx.x * blockDim.x + threadIdx.x) >> 5);
    int lane = threadIdx.x & 31;
    if (gw < nsrc) {
        float s = 0.f;
        if (lane < 16) {
            float4 v = ((const float4*)g_z)[gw * 16 + lane];
            float4 a = ((const float4*)attn)[lane];  // a_l = attn[0:64]
            s = v.x * a.x + v.y * a.y + v.z * a.z + v.w * a.w;
        }
#pragma unroll
        for (int o = 16; o > 0; o >>= 1) s += __shfl_down_sync(0xffffffffu, s, o);
        if (lane == 0) g_el[gw] = s;
    } else {
        int node = gw - nsrc;
        if (node < ndst) {
            float4 v = ((const float4*)hdst)[node * 32 + lane];
            float4 w = g_wr[lane];
            float s = v.x * w.x + v.y * w.y + v.z * w.z + v.w * w.w;
#pragma unroll
            for (int o = 16; o > 0; o >>= 1) s += __shfl_down_sync(0xffffffffu, s, o);
            if (lane == 0) g_er[node] = s;
        }
    }
}

// ---------------------------------------------------------------------------
__global__ void init_kernel(float4* __restrict__ out4, int n_out4, int ndst) {
    int i = blockIdx.x * blockDim.x + threadIdx.x;
    if (i < n_out4) out4[i] = make_float4(0.f, 0.f, 0.f, 0.f);
    if (i < ndst) {
        g_m[i] = __int_as_float(0xFF800000);  // -inf
        g_den[i] = 0.f;
    }
}

// ---------------------------------------------------------------------------
__global__ void edge_max_kernel(const int* __restrict__ src,
                                const int* __restrict__ dst, int ne) {
    int i = blockIdx.x * blockDim.x + threadIdx.x;
    if (i >= ne) return;
    int s = src[i], d = dst[i];
    float e = g_el[s] + g_er[d];
    e = (e > 0.f) ? e : 0.01f * e;  // leaky_relu
    g_e[i] = e;
    if (e >= 0.f)
        atomicMax((int*)(g_m + d), __float_as_int(e));
    else
        atomicMin((unsigned int*)(g_m + d), __float_as_uint(e));
}

// ---------------------------------------------------------------------------
__global__ void edge_exp_kernel(const int* __restrict__ dst, int ne) {
    int i = blockIdx.x * blockDim.x + threadIdx.x;
    if (i >= ne) return;
    int d = dst[i];
    float ex = __expf(g_e[i] - g_m[d]);
    g_e[i] = ex;
    atomicAdd(g_den + d, ex);
}

// ---------------------------------------------------------------------------
// h_out[dst] += (ex/denom[dst]) * z_src[src]; 16 lanes/edge, red.v4
__global__ void scatter_kernel(const int* __restrict__ src,
                               const int* __restrict__ dst,
                               float* __restrict__ out, int ne) {
    int t = blockIdx.x * blockDim.x + threadIdx.x;
    int edge = t >> 4;
    int l = t & 15;
    if (edge >= ne) return;
    int s = src[edge], d = dst[edge];
    float alpha = g_e[edge] / g_den[d];
    float4 v = ((const float4*)g_z)[s * 16 + l];
    float* p = out + (size_t)d * OUTD + l * 4;
    asm volatile("red.global.add.v4.f32 [%0], {%1, %2, %3, %4};" ::"l"(p),
                 "f"(v.x * alpha), "f"(v.y * alpha), "f"(v.z * alpha),
                 "f"(v.w * alpha)
                 : "memory");
}

// ---------------------------------------------------------------------------
extern "C" void kernel_launch(void* const* d_in, const int* in_sizes, int n_in,
                              void* d_out, int out_size) {
    const float* h_src = (const float*)d_in[0];
    const float* h_dst = (const float*)d_in[1];
    const int* src_idx = (const int*)d_in[2];
    const int* dst_idx = (const int*)d_in[3];
    const float* W_src = (const float*)d_in[4];
    const float* W_dst = (const float*)d_in[5];
    const float* attn = (const float*)d_in[6];
    const int* item_user = (const int*)d_in[7];

    int nsrc = in_sizes[0] / IND;
    int ndst = in_sizes[1] / IND;
    int ne = in_sizes[2];
    float* out = (float*)d_out;

    wr_kernel<<<1, 128>>>(W_dst, attn);
    gemm_z_kernel<<<(nsrc + 63) / 64, 256>>>(h_src, W_src, item_user, nsrc);

    int tot_threads = (nsrc + ndst) * 32;
    el_er_kernel<<<(tot_threads + 255) / 256, 256>>>(h_dst, attn, nsrc, ndst);

    int n_out4 = out_size / 4;
    int init_n = (n_out4 > ndst) ? n_out4 : ndst;
    init_kernel<<<(init_n + 255) / 256, 256>>>((float4*)out, n_out4, ndst);

    edge_max_kernel<<<(ne + 255) / 256, 256>>>(src_idx, dst_idx, ne);
    edge_exp_kernel<<<(ne + 255) / 256, 256>>>(dst_idx, ne);

    long long st = (long long)ne * 16;
    scatter_kernel<<<(unsigned)((st + 255) / 256), 256>>>(src_idx, dst_idx, out, ne);
}